// round 16
// baseline (speedup 1.0000x reference)
#include <cuda_runtime.h>
#include <cuda_bf16.h>
#include <math.h>

#define BS 16
#define Q 900
#define NC 92
#define TPB 100
#define NT 1600
#define C_ELEMS (16*900*1600)
#define ROW_F4 (Q/4)             // 225 float4 per row
#define QPB 8
#define QT 113                   // ceil(900/8) query tiles per batch
#define SLICE_BLOCKS (QT*BS)     // 1808
#define COST_OFF (BS + SLICE_BLOCKS)          // 1824
#define TOTAL_BLOCKS (COST_OFF + (BS*Q)/QPB)  // 3624
#define NTHR 256

__device__ float4 g_ctr4[BS * TPB * ROW_F4];
__device__ int    g_done[BS];    // per-batch slice-completion counters (self-resetting)

// ---------------------------------------------------------------------------
__device__ __forceinline__ int detect_mode_block(const unsigned int* __restrict__ ids)
{
    int ok = 1;
    for (int k = threadIdx.x; k < 800; k += NTHR) {
        unsigned lo = ids[2*k], hi = ids[2*k+1];
        if (hi != 0u || lo >= 92u) ok = 0;
    }
    return __syncthreads_and(ok);
}

// ---------------------------------------------------------------------------
struct LsaSh {
    double u[TPB + 4];
    int    p[Q + 8];
    int    way[Q + 8];
    unsigned long long s_em[2][8];   // 16B-aligned, 64B per parity
    int    s_j[2][8];
    int    s_p[2][8];
    int    ans[TPB];
};
struct SliceSh {
    float4 tb[TPB];
    int    id[TPB];
    float  prob[QPB][NC];
    float  box[QPB][4];
    float  outv[TPB][QPB];
};
struct CostSh {
    float4 tb[NT];
    int    id[NT];
    float  prob[QPB][NC];
    float  box[QPB][4];
};
union AllSh { LsaSh l; SliceSh s; CostSh c; };

// ---------------------------------------------------------------------------
__device__ __forceinline__ unsigned long long enc64(double x)
{
    long long b = __double_as_longlong(x);
    return (unsigned long long)(b ^ ((b >> 63) | 0x8000000000000000LL));
}
__device__ __forceinline__ double dec64(unsigned long long e)
{
    long long b = (long long)e;
    b ^= ((~b) >> 63) | 0x8000000000000000LL;
    return __longlong_as_double(b);
}

// ---------------------------------------------------------------------------
__device__ void slice_block(SliceSh* sh, int b, int qtile,
                            const float* __restrict__ logits,
                            const float* __restrict__ boxes,
                            const void*  __restrict__ ids,
                            const float* __restrict__ tbox)
{
    const int tid = threadIdx.x;
    const int w = tid >> 5, lane = tid & 31;
    const int q0 = qtile * QPB;
    const int mode = detect_mode_block((const unsigned int*)ids);

    const float4* tb4 = (const float4*)tbox;
    if (tid < TPB) sh->tb[tid] = tb4[b * TPB + tid];
    if (mode) {
        const long long* id64 = (const long long*)ids;
        if (tid < TPB) sh->id[tid] = (int)id64[b * TPB + tid];
    } else {
        const int* id32 = (const int*)ids;
        if (tid < TPB) sh->id[tid] = id32[b * TPB + tid];
    }

    {
        int r = w;
        int q = q0 + r;
        if (r < QPB && q < Q) {
            const float* lr = logits + ((size_t)(b * Q + q)) * NC;
            float x0 = lr[lane];
            float x1 = lr[lane + 32];
            float x2 = (lane + 64 < NC) ? lr[lane + 64] : -1e30f;
            float m = fmaxf(x0, fmaxf(x1, x2));
            for (int o = 16; o; o >>= 1) m = fmaxf(m, __shfl_xor_sync(~0u, m, o));
            float e0 = expf(x0 - m);
            float e1 = expf(x1 - m);
            float e2 = (lane + 64 < NC) ? expf(x2 - m) : 0.0f;
            float s = e0 + e1 + e2;
            for (int o = 16; o; o >>= 1) s += __shfl_xor_sync(~0u, s, o);
            float inv = 1.0f / s;
            sh->prob[r][lane]      = e0 * inv;
            sh->prob[r][lane + 32] = e1 * inv;
            if (lane + 64 < NC) sh->prob[r][lane + 64] = e2 * inv;
            if (lane < 4) sh->box[r][lane] = boxes[((size_t)(b * Q + q)) * 4 + lane];
        }
    }
    __syncthreads();

    for (int r = 0; r < QPB; r++) {
        int q = q0 + r;
        if (q >= Q) break;
        const float pcx = sh->box[r][0], pcy = sh->box[r][1];
        const float pw  = sh->box[r][2], ph  = sh->box[r][3];
        const float px0 = pcx - pw * 0.5f, py0 = pcy - ph * 0.5f;
        const float px1 = pcx + pw * 0.5f, py1 = pcy + ph * 0.5f;
        const float pa  = (px1 - px0) * (py1 - py0);
        if (tid < TPB) {
            float4 t = sh->tb[tid];
            float tx0 = t.x, ty0 = t.y, tx1 = t.z, ty1 = t.w;
            float tcx = (tx0 + tx1) * 0.5f, tcy = (ty0 + ty1) * 0.5f;
            float tw = tx1 - tx0, th = ty1 - ty0;
            float cbb = fabsf(pcx - tcx) + fabsf(pcy - tcy)
                      + fabsf(pw - tw) + fabsf(ph - th);
            float ta = tw * th;
            float ix0 = fmaxf(px0, tx0), iy0 = fmaxf(py0, ty0);
            float ix1 = fminf(px1, tx1), iy1 = fminf(py1, ty1);
            float iw = fmaxf(ix1 - ix0, 0.0f), ih = fmaxf(iy1 - iy0, 0.0f);
            float inter = iw * ih;
            float uni = pa + ta - inter;
            float iou = inter / uni;
            float ex0 = fminf(px0, tx0), ey0 = fminf(py0, ty0);
            float ex1 = fmaxf(px1, tx1), ey1 = fmaxf(py1, ty1);
            float cw = fmaxf(ex1 - ex0, 0.0f), ch = fmaxf(ey1 - ey0, 0.0f);
            float ca = cw * ch;
            float giou = iou - (ca - uni) / ca;
            sh->outv[tid][r] = 5.0f * cbb - sh->prob[r][sh->id[tid]] - 2.0f * giou;
        }
    }
    __syncthreads();

    float* g_ctrf = (float*)g_ctr4;
    for (int idx = tid; idx < TPB * QPB; idx += NTHR) {
        int t = idx >> 3, r = idx & 7;
        int q = q0 + r;
        if (q < Q)
            g_ctrf[b * (TPB * Q) + t * Q + q] = sh->outv[t][r];
    }

    __syncthreads();
    __threadfence();
    if (tid == 0) atomicAdd(&g_done[b], 1);
}

// ---------------------------------------------------------------------------
__device__ void cost_block(CostSh* sh, int tile,
                           const float* __restrict__ logits,
                           const float* __restrict__ boxes,
                           const void*  __restrict__ ids,
                           const float* __restrict__ tbox,
                           float* __restrict__ C)
{
    const int tid = threadIdx.x;
    const int base_bq = tile * QPB;
    const int mode = detect_mode_block((const unsigned int*)ids);

    const float4* tb4 = (const float4*)tbox;
    for (int x = tid; x < NT; x += NTHR) sh->tb[x] = tb4[x];
    if (mode) {
        const long long* id64 = (const long long*)ids;
        for (int x = tid; x < NT; x += NTHR) sh->id[x] = (int)id64[x];
    } else {
        const int* id32 = (const int*)ids;
        for (int x = tid; x < NT; x += NTHR) sh->id[x] = id32[x];
    }

    const int w = tid >> 5, lane = tid & 31;
    {
        int r = w;
        if (r < QPB) {
            int bq = base_bq + r;
            const float* lr = logits + (size_t)bq * NC;
            float x0 = lr[lane];
            float x1 = lr[lane + 32];
            float x2 = (lane + 64 < NC) ? lr[lane + 64] : -1e30f;
            float m = fmaxf(x0, fmaxf(x1, x2));
            for (int o = 16; o; o >>= 1) m = fmaxf(m, __shfl_xor_sync(~0u, m, o));
            float e0 = expf(x0 - m);
            float e1 = expf(x1 - m);
            float e2 = (lane + 64 < NC) ? expf(x2 - m) : 0.0f;
            float s = e0 + e1 + e2;
            for (int o = 16; o; o >>= 1) s += __shfl_xor_sync(~0u, s, o);
            float inv = 1.0f / s;
            sh->prob[r][lane]      = e0 * inv;
            sh->prob[r][lane + 32] = e1 * inv;
            if (lane + 64 < NC) sh->prob[r][lane + 64] = e2 * inv;
            if (lane < 4) sh->box[r][lane] = boxes[(size_t)bq * 4 + lane];
        }
    }
    __syncthreads();

    for (int r = 0; r < QPB; r++) {
        const int bq = base_bq + r;
        const float pcx = sh->box[r][0], pcy = sh->box[r][1];
        const float pw  = sh->box[r][2], ph  = sh->box[r][3];
        const float px0 = pcx - pw * 0.5f, py0 = pcy - ph * 0.5f;
        const float px1 = pcx + pw * 0.5f, py1 = pcy + ph * 0.5f;
        const float pa  = (px1 - px0) * (py1 - py0);
        float* Crow = C + (size_t)bq * NT;
        for (int j = tid; j < NT; j += NTHR) {
            float4 t = sh->tb[j];
            float tx0 = t.x, ty0 = t.y, tx1 = t.z, ty1 = t.w;
            float tcx = (tx0 + tx1) * 0.5f, tcy = (ty0 + ty1) * 0.5f;
            float tw = tx1 - tx0, th = ty1 - ty0;
            float cbb = fabsf(pcx - tcx) + fabsf(pcy - tcy)
                      + fabsf(pw - tw) + fabsf(ph - th);
            float ta = tw * th;
            float ix0 = fmaxf(px0, tx0), iy0 = fmaxf(py0, ty0);
            float ix1 = fminf(px1, tx1), iy1 = fminf(py1, ty1);
            float iw = fmaxf(ix1 - ix0, 0.0f), ih = fmaxf(iy1 - iy0, 0.0f);
            float inter = iw * ih;
            float uni = pa + ta - inter;
            float iou = inter / uni;
            float ex0 = fminf(px0, tx0), ey0 = fminf(py0, ty0);
            float ex1 = fmaxf(px1, tx1), ey1 = fmaxf(py1, ty1);
            float cw = fmaxf(ex1 - ex0, 0.0f), ch = fmaxf(ey1 - ey0, 0.0f);
            float ca = cw * ch;
            float giou = iou - (ca - uni) / ca;
            Crow[j] = 5.0f * cbb - sh->prob[r][sh->id[j]] - 2.0f * giou;
        }
    }
}

// ---------------------------------------------------------------------------
// LSA role, 256 threads: 4 columns/thread. p register-mirrored per round
// (p is static within a round; refreshed under the round-end barrier), so
// the winner lane publishes p from registers — no LDS on the pre-barrier
// critical path. Reference-exact fp64 sequence.
// ---------------------------------------------------------------------------
__device__ void lsa_block(LsaSh* sh, int b, float* __restrict__ out)
{
    const int tid = threadIdx.x;
    const int w = tid >> 5, lane = tid & 31;
    const bool act = (tid < ROW_F4);           // 225 active threads

    double v[4];
    int rowof[4];
    int p_reg[4];                              // mirror of p for own columns
#pragma unroll
    for (int k = 0; k < 4; k++) { v[k] = 0.0; rowof[k] = 0; p_reg[k] = 0; }
    const int col0 = 4 * tid;                  // colv[k] = col0 + k

    for (int x = tid; x <= Q; x += NTHR) sh->p[x] = 0;
    if (tid <= TPB) sh->u[tid] = 0.0;

    if (tid == 0) {
        volatile int* dv = &g_done[b];
        while (*dv < QT) { }
    }
    __syncthreads();
    __threadfence();

    const float4* cb4 = g_ctr4 + b * (TPB * ROW_F4);

    float4 nxt0 = act ? __ldg(&cb4[tid]) : make_float4(0.f,0.f,0.f,0.f);

    int par = 0;

    for (int i = 1; i <= TPB; i++) {
        if (tid == 0) sh->p[0] = i;
        double minv[4];
        unsigned long long em[4];
        unsigned usedm = 0;

        float rwf[4] = { nxt0.x, nxt0.y, nxt0.z, nxt0.w };
        unsigned long long bestE = ~0ULL; int bestJ = Q + 2;
#pragma unroll
        for (int k = 0; k < 4; k++) {
            if (act) {
                double cur = ((double)rwf[k] - 0.0) - v[k];
                minv[k] = cur; em[k] = enc64(cur); sh->way[col0 + k + 1] = 0;
                if (em[k] < bestE) { bestE = em[k]; bestJ = col0 + k + 1; }
            } else { minv[k] = 1e300; em[k] = ~0ULL; }
        }

        if (i < TPB && act) nxt0 = __ldg(&cb4[i * ROW_F4 + tid]);

        while (true) {
            // ---- warp argmin; winner lane publishes p from REGISTERS ----
            unsigned hi  = (unsigned)(bestE >> 32);
            unsigned mhi = __reduce_min_sync(0xffffffffu, hi);
            unsigned bal = __ballot_sync(0xffffffffu, hi == mhi);
            if (__popc(bal) == 1) {
                int src = __ffs(bal) - 1;
                if (lane == src) {
                    int idx = bestJ - 1 - col0;          // 0..3 (own column)
                    int wp = p_reg[0];
                    if (idx == 1) wp = p_reg[1];
                    if (idx == 2) wp = p_reg[2];
                    if (idx == 3) wp = p_reg[3];
                    sh->s_em[par][w] = bestE;
                    sh->s_j[par][w]  = bestJ;
                    sh->s_p[par][w]  = wp;
                }
            } else {
                unsigned lo  = (hi == mhi) ? (unsigned)bestE : 0xffffffffu;
                unsigned mlo = __reduce_min_sync(0xffffffffu, lo);
                unsigned cjj = (hi == mhi && (unsigned)bestE == mlo)
                               ? (unsigned)bestJ : 0x7fffffffu;
                unsigned mj  = __reduce_min_sync(0xffffffffu, cjj);
                if ((unsigned)bestJ == mj) {
                    int idx = bestJ - 1 - col0;
                    int wp = p_reg[0];
                    if (idx == 1) wp = p_reg[1];
                    if (idx == 2) wp = p_reg[2];
                    if (idx == 3) wp = p_reg[3];
                    sh->s_em[par][w] = ((unsigned long long)mhi << 32) | mlo;
                    sh->s_j[par][w]  = mj;
                    sh->s_p[par][w]  = wp;
                }
            }
            __syncthreads();                                   // ONE barrier

            // vector LDS for the 8 candidate keys (64B = 2 x uint4 x 2)
            unsigned long long ce[8]; int cj[8], cp[8], ci[8];
            {
                const uint4* pe = (const uint4*)&sh->s_em[par][0];
                uint4 e01 = pe[0], e23 = pe[1], e45 = pe[2], e67 = pe[3];
                ce[0] = ((unsigned long long)e01.y << 32) | e01.x;
                ce[1] = ((unsigned long long)e01.w << 32) | e01.z;
                ce[2] = ((unsigned long long)e23.y << 32) | e23.x;
                ce[3] = ((unsigned long long)e23.w << 32) | e23.z;
                ce[4] = ((unsigned long long)e45.y << 32) | e45.x;
                ce[5] = ((unsigned long long)e45.w << 32) | e45.z;
                ce[6] = ((unsigned long long)e67.y << 32) | e67.x;
                ce[7] = ((unsigned long long)e67.w << 32) | e67.z;
                const uint4* pj = (const uint4*)&sh->s_j[par][0];
                uint4 j03 = pj[0], j47 = pj[1];
                cj[0] = j03.x; cj[1] = j03.y; cj[2] = j03.z; cj[3] = j03.w;
                cj[4] = j47.x; cj[5] = j47.y; cj[6] = j47.z; cj[7] = j47.w;
                const uint4* pp = (const uint4*)&sh->s_p[par][0];
                uint4 p03 = pp[0], p47 = pp[1];
                cp[0] = p03.x; cp[1] = p03.y; cp[2] = p03.z; cp[3] = p03.w;
                cp[4] = p47.x; cp[5] = p47.y; cp[6] = p47.z; cp[7] = p47.w;
            }
#pragma unroll
            for (int s = 0; s < 8; s++) ci[s] = s;

            // issue all 8 candidate-row loads NOW (1 float4 each)
            float4 ra[8];
#pragma unroll
            for (int s = 0; s < 8; s++) {
                if (cp[s] && act)
                    ra[s] = __ldg(&cb4[(cp[s] - 1) * ROW_F4 + tid]);
            }

            // depth-3 tree reduce (ties -> smaller j), track winner slot
#pragma unroll
            for (int st = 1; st < 8; st <<= 1) {
#pragma unroll
                for (int k = 0; k < 8; k += 2 * st) {
                    if (ce[k + st] < ce[k] ||
                        (ce[k + st] == ce[k] && cj[k + st] < cj[k])) {
                        ce[k] = ce[k + st]; cj[k] = cj[k + st];
                        cp[k] = cp[k + st]; ci[k] = ci[k + st];
                    }
                }
            }
            const unsigned long long de = ce[0];
            const int j1 = cj[0], i1 = cp[0], ww = ci[0];
            const double delta = dec64(de);

            if (i1 == 0) {
#pragma unroll
                for (int k = 0; k < 4; k++) {
                    if (act && ((usedm >> k) & 1u)) {
                        v[k] -= delta; sh->u[rowof[k]] += delta;
                    }
                }
                if (tid == 0) {
                    sh->u[i] += delta;
                    int jj = j1;
                    while (jj) { int jp = sh->way[jj]; sh->p[jj] = sh->p[jp]; jj = jp; }
                }
                par ^= 1;
                break;
            }

            // u[i1]: safe unordered read (row i1 gets no u update this iter)
            const double ui1 = sh->u[i1];

            // winner row registers (8-way select)
            float4 wsel = ra[0];
#pragma unroll
            for (int s = 1; s < 8; s++) if (ww == s) wsel = ra[s];
            rwf[0] = wsel.x; rwf[1] = wsel.y; rwf[2] = wsel.z; rwf[3] = wsel.w;

            // cur/ec hoisted BEFORE pass1 (v of unused cols unchanged by the
            // update; used cols never consume cur)
            double curv[4]; unsigned long long ec[4];
#pragma unroll
            for (int k = 0; k < 4; k++) {
                double t1 = (double)rwf[k] - ui1;
                curv[k] = t1 - v[k];
                ec[k] = enc64(curv[k]);
            }

            // ---- PASS 1: dual updates + m2 (reference order) ----
#pragma unroll
            for (int k = 0; k < 4; k++) {
                if (act) {
                    if ((usedm >> k) & 1u) {
                        v[k] -= delta; sh->u[rowof[k]] += delta;
                    } else if (col0 + k + 1 != j1) {
                        minv[k] -= delta;
                        em[k] = enc64(minv[k]);
                    }
                }
            }
            if (tid == 0) sh->u[i] += delta;

            // ---- PASS 2: merge cur vs m2, tree best-tracking ----
            unsigned long long be[4]; int bj[4];
#pragma unroll
            for (int k = 0; k < 4; k++) {
                bool a2 = act && !((usedm >> k) & 1u) && (col0 + k + 1 != j1);
                bj[k] = col0 + k + 1;
                if (a2) {
                    if (ec[k] < em[k]) { minv[k] = curv[k]; em[k] = ec[k]; sh->way[bj[k]] = j1; }
                    be[k] = em[k];
                } else {
                    be[k] = ~0ULL;
                }
            }
#pragma unroll
            for (int s = 1; s < 4; s <<= 1) {
#pragma unroll
                for (int k = 0; k < 4; k += 2 * s) {
                    if (be[k + s] < be[k] ||
                        (be[k + s] == be[k] && bj[k + s] < bj[k])) {
                        be[k] = be[k + s]; bj[k] = bj[k + s];
                    }
                }
            }
            bestE = be[0]; bestJ = bj[0];

            {
                int c = j1 - 1;
                if ((c >> 2) == tid) {
                    usedm |= 1u << (c & 3);
                    rowof[c & 3] = i1;
                    p_reg[c & 3] = i1;   // keep mirror coherent (p[j1]=i1 conceptually
                                         // happens at round end, but p_reg for used
                                         // columns is never consumed again this round)
                }
            }
            par ^= 1;
        }

        __syncthreads();   // path-walk p[] writes visible before refresh

        // refresh p mirror for own columns (p static during next round)
        if (act) {
#pragma unroll
            for (int k = 0; k < 4; k++) p_reg[k] = sh->p[col0 + k + 1];
        }
    }

#pragma unroll
    for (int k = 0; k < 4; k++) {
        if (act) {
            int j = col0 + k + 1;
            if (sh->p[j] > 0) sh->ans[sh->p[j] - 1] = j - 1;
        }
    }
    __syncthreads();
    if (tid < TPB) {
        int a = sh->ans[tid];
        int rank = 0;
        for (int t2 = 0; t2 < TPB; t2++) rank += (sh->ans[t2] < a) ? 1 : 0;
        out[(size_t)C_ELEMS + (size_t)b * TPB + rank]                    = (float)a;
        out[(size_t)C_ELEMS + (size_t)BS * TPB + (size_t)b * TPB + rank] = (float)tid;
    }
    __syncthreads();
    if (tid == 0) atomicSub(&g_done[b], QT);   // restore 0 for next replay
}

// ---------------------------------------------------------------------------
__global__ void __launch_bounds__(NTHR, 1) mega_kernel(
    const float* __restrict__ logits,
    const float* __restrict__ boxes,
    const void*  __restrict__ ids,
    const float* __restrict__ tbox,
    float* __restrict__ out)
{
    __shared__ AllSh sh;
    const int bid = blockIdx.x;
    if (bid < BS) {
        lsa_block(&sh.l, bid, out);
    } else if (bid < COST_OFF) {
        int sidx = bid - BS;
        slice_block(&sh.s, sidx & 15, sidx >> 4, logits, boxes, ids, tbox);
    } else {
        cost_block(&sh.c, bid - COST_OFF, logits, boxes, ids, tbox, out);
    }
}

// ---------------------------------------------------------------------------
extern "C" void kernel_launch(void* const* d_in, const int* in_sizes, int n_in,
                              void* d_out, int out_size)
{
    const float* logits = (const float*)d_in[0];
    const float* boxes  = (const float*)d_in[1];
    const void*  ids    = d_in[2];
    const float* tbox   = (const float*)d_in[3];
    float* out = (float*)d_out;

    mega_kernel<<<TOTAL_BLOCKS, NTHR>>>(logits, boxes, ids, tbox, out);
}